// round 8
// baseline (speedup 1.0000x reference)
#include <cuda_runtime.h>
#include <cuda_bf16.h>
#include <mma.h>
using namespace nvcuda;
typedef __nv_bfloat16 bf;

#define NN 50000
#define EE 800000
#define NFD 64
#define EFD 32
#define HH 96
#define OUTD 64
#define LL 4
#define GG 64
#define NH (NN*HH)
#define SMB 83968   // dynamic smem: Cs 49152 + Ah/Al 20480 + Wh/Wl 13312 (+pad)

// ------------------------------ scratch ------------------------------------
__device__ float d_f[3*NH + LL*HH];                       // PT, PS, AGG, bcomb
__device__ unsigned d_p[NN*NFD + 2*NH + GG*HH + (size_t)EE*EFD]; // xp,hp,h2p,gmp,eap
// packed weights: ewp1 6144 | ewp2 9216 | mwp 86016 | wu1p 73728 | uw2p 36864 | hw1p 9216 | hw2p 6144
__device__ unsigned d_wp[227328];
// deg[NN], gcnt[GG+1] | rowptr[NN+1], cursor[NN], srcs[EE], ctgt[EE], eids[EE], gstart[GG+1]
__device__ int d_i[NN + (GG+1) + (NN+1) + NN + 3*EE + (GG+1)];

__device__ __forceinline__ unsigned packsplit(float x) {
    bf h = __float2bfloat16_rn(x);
    bf l = __float2bfloat16_rn(x - __bfloat162float(h));
    return ((unsigned)__bfloat16_as_ushort(l) << 16) | (unsigned)__bfloat16_as_ushort(h);
}
__device__ __forceinline__ void split1(float x, bf& h, bf& l) {
    h = __float2bfloat16_rn(x);
    l = __float2bfloat16_rn(x - __bfloat162float(h));
}

// ------------------------------ setup --------------------------------------
__global__ void hist_both(const int* __restrict__ tgt, const int* __restrict__ batch,
                          int* __restrict__ deg, int* __restrict__ gcnt) {
    int i = blockIdx.x*blockDim.x + threadIdx.x;
    if (i < EE) atomicAdd(&deg[tgt[i]], 1);
    else if (i < EE + NN) atomicAdd(&gcnt[batch[i - EE]], 1);
}

__device__ void scan_seg(const int* __restrict__ in, int* __restrict__ out,
                         int* __restrict__ copy, int n, int* sums) {
    int lane = threadIdx.x & 31, wid = threadIdx.x >> 5, nwarp = blockDim.x >> 5;
    int offset = 0;
    for (int base = 0; base < n; base += blockDim.x) {
        int i = base + threadIdx.x;
        int v = (i < n) ? in[i] : 0, x = v;
        #pragma unroll
        for (int d = 1; d < 32; d <<= 1) { int y = __shfl_up_sync(~0u, x, d); if (lane >= d) x += y; }
        if (lane == 31) sums[wid] = x;
        __syncthreads();
        if (wid == 0) {
            int s = (lane < nwarp) ? sums[lane] : 0;
            #pragma unroll
            for (int d = 1; d < 32; d <<= 1) { int y = __shfl_up_sync(~0u, s, d); if (lane >= d) s += y; }
            sums[lane] = s;
        }
        __syncthreads();
        int warp_off = (wid > 0) ? sums[wid-1] : 0;
        if (i < n) { int val = offset + warp_off + x - v; out[i] = val; if (copy) copy[i] = val; }
        int total = sums[nwarp-1];
        __syncthreads();
        offset += total;
    }
    if (threadIdx.x == 0) out[n] = offset;
    __syncthreads();
}
__global__ void scan_both(const int* __restrict__ deg, int* __restrict__ rowptr,
                          int* __restrict__ cursor, const int* __restrict__ gcnt,
                          int* __restrict__ gstart) {
    __shared__ int sums[32];
    scan_seg(deg, rowptr, cursor, NN, sums);
    scan_seg(gcnt, gstart, nullptr, GG, sums);
}

__global__ void scatter_kernel(const int* __restrict__ src, const int* __restrict__ tgt,
                               int* __restrict__ cursor, int* __restrict__ srcs,
                               int* __restrict__ eids, int* __restrict__ ctgt) {
    int e = blockIdx.x*blockDim.x + threadIdx.x;
    if (e < EE) {
        int t = tgt[e];
        int p = atomicAdd(&cursor[t], 1);
        srcs[p] = src[e]; eids[p] = e; ctgt[p] = t;
    }
}

// split x -> xp; gather edge_attr (CSR order) -> eap  (one launch)
__global__ void gather_split(const float* __restrict__ x, const float* __restrict__ EA,
                             const int* __restrict__ eids,
                             unsigned* __restrict__ xp, unsigned* __restrict__ eap) {
    long long idx = (long long)blockIdx.x*blockDim.x + threadIdx.x;
    if (idx < NN*NFD) xp[idx] = packsplit(x[idx]);
    else {
        long long j = idx - NN*NFD;
        if (j < (long long)EE*EFD) {
            int i = (int)(j >> 5), f = (int)(j & 31);
            eap[j] = packsplit(EA[(size_t)eids[i]*EFD + f]);
        }
    }
}

struct PackArgs { const float* src[10]; unsigned* dst[10]; int n[10]; };
__global__ void pack_kernel(PackArgs a) {
    int s = blockIdx.y;
    int i = blockIdx.x*blockDim.x + threadIdx.x;
    if (i < a.n[s]) a.dst[s][i] = packsplit(a.src[s][i]);
}

// Wcomb[l] = msg_w2[l] @ Ubot[l] -> packed into wu1p rows 96..191; bcomb = msg_b2@Ubot
__global__ void wcomb_kernel(const float* __restrict__ msg_w2, const float* __restrict__ msg_b2,
                             const float* __restrict__ upd_w1,
                             unsigned* __restrict__ wu1p, float* __restrict__ bcomb) {
    int l = blockIdx.x;
    const float* mw2 = msg_w2 + (size_t)l*HH*HH;
    const float* Ubot = upd_w1 + (size_t)l*2*HH*HH + HH*HH;
    for (int idx = threadIdx.x; idx < HH*HH; idx += blockDim.x) {
        int k = idx / HH, c = idx - k*HH;
        float s = 0.f;
        for (int j = 0; j < HH; j++) s += mw2[k*HH + j] * Ubot[j*HH + c];
        wu1p[(size_t)l*2*HH*HH + (HH + k)*HH + c] = packsplit(s);
    }
    const float* mb2 = msg_b2 + l*HH;
    for (int c = threadIdx.x; c < HH; c += blockDim.x) {
        float s = 0.f;
        for (int j = 0; j < HH; j++) s += mb2[j] * Ubot[j*HH + c];
        bcomb[l*HH + c] = s;
    }
}

// --------------------------- MMA helper ------------------------------------
__device__ __forceinline__ void do_mma32(
    wmma::fragment<wmma::accumulator,16,16,16,float> (&acc)[2][3],
    const bf* Ah, const bf* Al, const bf* Wh, const bf* Wl, int wm, int wn) {
    #pragma unroll
    for (int ks = 0; ks < 32; ks += 16) {
        wmma::fragment<wmma::matrix_a,16,16,16,bf,wmma::row_major> ah[2], al2[2];
        wmma::fragment<wmma::matrix_b,16,16,16,bf,wmma::row_major> bh[3], bl[3];
        #pragma unroll
        for (int i = 0; i < 2; i++) {
            wmma::load_matrix_sync(ah[i],  &Ah[(wm + i*16)*40 + ks], 40);
            wmma::load_matrix_sync(al2[i], &Al[(wm + i*16)*40 + ks], 40);
        }
        #pragma unroll
        for (int j = 0; j < 3; j++) {
            wmma::load_matrix_sync(bh[j], &Wh[ks*104 + wn + j*16], 104);
            wmma::load_matrix_sync(bl[j], &Wl[ks*104 + wn + j*16], 104);
        }
        #pragma unroll
        for (int i = 0; i < 2; i++)
            #pragma unroll
            for (int j = 0; j < 3; j++) {
                wmma::mma_sync(acc[i][j], ah[i],  bh[j], acc[i][j]);
                wmma::mma_sync(acc[i][j], ah[i],  bl[j], acc[i][j]);
                wmma::mma_sync(acc[i][j], al2[i], bh[j], acc[i][j]);
            }
    }
}

// --------------------------- fused MLP (1 or 2 stages) ----------------------
// stage1: A = [A1p packed (K1) | A2f fp32/deg (K-K1)] @ W1 (packed [K x 96])
//   epilogue1: + b1 (+ b1extra if degmask[row]>0), optional relu -> Cs (or out)
// stage2 (if W2p): Cs @ W2p (packed [96 x N2]) + b2, optional relu -> out
// dual (gridDim.y==2): blockIdx.y selects W1a/W1b, b1a0/b1a1, oF0/oF1 (single-stage).
__global__ void __launch_bounds__(256) mlp_tc(
    const unsigned* __restrict__ A1p, int lda1, int K1, int K,
    float* __restrict__ A2f, int lda2, const int* __restrict__ Adeg, int zeroA2,
    const unsigned* __restrict__ W1a, const unsigned* __restrict__ W1b,
    const float* __restrict__ b1a0, const float* __restrict__ b1a1,
    const float* __restrict__ b1extra, const int* __restrict__ degmask, int relu1,
    const unsigned* __restrict__ W2p, const float* __restrict__ b2, int N2, int relu2,
    float* __restrict__ oF0, float* __restrict__ oF1, unsigned* __restrict__ oP,
    int ldO, int M)
{
    extern __shared__ char sm[];
    float* Cs = (float*)sm;                     // [128][96]
    bf* Ah = (bf*)(sm + 49152);                 // [128][40]
    bf* Al = Ah + 5120;
    bf* Wh = (bf*)(sm + 49152 + 20480);         // [32][104]
    bf* Wl = Wh + 3328;

    const unsigned* W1 = (blockIdx.y && W1b) ? W1b : W1a;
    const float* b1    = blockIdx.y ? b1a1 : b1a0;
    float* oF          = blockIdx.y ? oF1 : oF0;

    int tid = threadIdx.x, wid = tid >> 5;
    int bm0 = blockIdx.x * 128;
    int wm = (wid & 3) * 32, wn = (wid >> 2) * 48;

    wmma::fragment<wmma::accumulator,16,16,16,float> acc[2][3];
    #pragma unroll
    for (int i = 0; i < 2; i++)
        #pragma unroll
        for (int j = 0; j < 3; j++) wmma::fill_fragment(acc[i][j], 0.f);

    // ---------------- stage 1 ----------------
    for (int k0 = 0; k0 < K; k0 += 32) {
        if (k0 < K1) {
            #pragma unroll
            for (int p = tid; p < 2048; p += 256) {
                int r = p >> 4, kc = (p & 15) << 1;
                int row = bm0 + r;
                uint2 v = make_uint2(0u, 0u);
                if (row < M) v = *(const uint2*)(A1p + (size_t)row*lda1 + k0 + kc);
                *(unsigned*)&Ah[r*40+kc] = __byte_perm(v.x, v.y, 0x5410);
                *(unsigned*)&Al[r*40+kc] = __byte_perm(v.x, v.y, 0x7632);
            }
        } else {
            #pragma unroll
            for (int p = tid; p < 2048; p += 256) {
                int r = p >> 4, kc = (p & 15) << 1;
                int row = bm0 + r;
                float v0 = 0.f, v1 = 0.f;
                if (row < M) {
                    float rs = 1.f / (float)max(Adeg[row], 1);
                    float* a = A2f + (size_t)row*lda2 + (k0 - K1) + kc;
                    v0 = a[0] * rs; v1 = a[1] * rs;
                    if (zeroA2) { a[0] = 0.f; a[1] = 0.f; }
                }
                bf h0, l0, h1, l1; split1(v0, h0, l0); split1(v1, h1, l1);
                Ah[r*40+kc] = h0; Ah[r*40+kc+1] = h1;
                Al[r*40+kc] = l0; Al[r*40+kc+1] = l1;
            }
        }
        #pragma unroll
        for (int p = tid; p < 1536; p += 256) {
            int kk = p / 48, nc = (p % 48) * 2;
            uint2 v = *(const uint2*)(W1 + (size_t)(k0+kk)*96 + nc);
            *(unsigned*)&Wh[kk*104+nc] = __byte_perm(v.x, v.y, 0x5410);
            *(unsigned*)&Wl[kk*104+nc] = __byte_perm(v.x, v.y, 0x7632);
        }
        __syncthreads();
        do_mma32(acc, Ah, Al, Wh, Wl, wm, wn);
        __syncthreads();
    }
    #pragma unroll
    for (int i = 0; i < 2; i++)
        #pragma unroll
        for (int j = 0; j < 3; j++)
            wmma::store_matrix_sync(&Cs[(wm + i*16)*96 + wn + j*16], acc[i][j], 96,
                                    wmma::mem_row_major);
    __syncthreads();

    if (!W2p) {
        for (int p = tid; p < 12288; p += 256) {
            int r = p / 96, c = p - r*96;
            int row = bm0 + r;
            if (row >= M) continue;
            float v = Cs[p];
            if (b1) v += b1[c];
            if (relu1) v = fmaxf(v, 0.f);
            size_t o = (size_t)row*ldO + c;
            if (oF) oF[o] = v;
            if (oP) oP[o] = packsplit(v);
        }
        return;
    }

    // epilogue1 -> Cs in place
    for (int p = tid; p < 12288; p += 256) {
        int r = p / 96, c = p - r*96;
        int row = bm0 + r;
        if (row >= M) continue;
        float v = Cs[p] + b1[c];
        if (b1extra && degmask[row] > 0) v += b1extra[c];
        if (relu1) v = fmaxf(v, 0.f);
        Cs[p] = v;
    }
    __syncthreads();

    // ---------------- stage 2 (K2 = 96) ----------------
    #pragma unroll
    for (int i = 0; i < 2; i++)
        #pragma unroll
        for (int j = 0; j < 3; j++) wmma::fill_fragment(acc[i][j], 0.f);
    for (int k0 = 0; k0 < 96; k0 += 32) {
        #pragma unroll
        for (int p = tid; p < 2048; p += 256) {
            int r = p >> 4, kc = (p & 15) << 1;
            float v0 = Cs[r*96 + k0 + kc], v1 = Cs[r*96 + k0 + kc + 1];
            bf h0, l0, h1, l1; split1(v0, h0, l0); split1(v1, h1, l1);
            Ah[r*40+kc] = h0; Ah[r*40+kc+1] = h1;
            Al[r*40+kc] = l0; Al[r*40+kc+1] = l1;
        }
        #pragma unroll
        for (int p = tid; p < 1536; p += 256) {
            int kk = p / 48, nc = (p % 48) * 2;
            uint2 v = make_uint2(0u, 0u);
            if (nc < N2) v = *(const uint2*)(W2p + (size_t)(k0+kk)*N2 + nc);
            *(unsigned*)&Wh[kk*104+nc] = __byte_perm(v.x, v.y, 0x5410);
            *(unsigned*)&Wl[kk*104+nc] = __byte_perm(v.x, v.y, 0x7632);
        }
        __syncthreads();
        do_mma32(acc, Ah, Al, Wh, Wl, wm, wn);
        __syncthreads();
    }
    #pragma unroll
    for (int i = 0; i < 2; i++)
        #pragma unroll
        for (int j = 0; j < 3; j++)
            wmma::store_matrix_sync(&Cs[(wm + i*16)*96 + wn + j*16], acc[i][j], 96,
                                    wmma::mem_row_major);
    __syncthreads();
    for (int p = tid; p < 12288; p += 256) {
        int r = p / 96, c = p - r*96;
        int row = bm0 + r;
        if (row >= M || c >= N2) continue;
        float v = Cs[p];
        if (b2) v += b2[c];
        if (relu2) v = fmaxf(v, 0.f);
        size_t o = (size_t)row*ldO + c;
        if (oF0) oF0[o] = v;
        if (oP) oP[o] = packsplit(v);
    }
}

// ------------------------- fused edge kernel --------------------------------
__global__ void __launch_bounds__(256) edge_fused(
    const unsigned* __restrict__ eap, const unsigned* __restrict__ W1cp,
    const float* __restrict__ PT, const float* __restrict__ PS,
    const int* __restrict__ csrc, const int* __restrict__ ctgt,
    float* __restrict__ AGG)
{
    __shared__ __align__(16) char smraw[49152];
    bf* Ah = (bf*)smraw;
    bf* Al = Ah + 5120;
    bf* Wh = Al + 5120;
    bf* Wl = Wh + 3328;
    float* pes = (float*)smraw;     // [128][96] (reused after mma)

    int tid = threadIdx.x, wid = tid >> 5, lane = tid & 31;
    int e0 = blockIdx.x * 128;
    int wm = (wid & 3) * 32, wn = (wid >> 2) * 48;

    #pragma unroll
    for (int p = tid; p < 2048; p += 256) {
        int r = p >> 4, kc = (p & 15) << 1;
        uint2 v = *(const uint2*)(eap + (size_t)(e0 + r)*EFD + kc);
        *(unsigned*)&Ah[r*40+kc] = __byte_perm(v.x, v.y, 0x5410);
        *(unsigned*)&Al[r*40+kc] = __byte_perm(v.x, v.y, 0x7632);
    }
    #pragma unroll
    for (int p = tid; p < 1536; p += 256) {
        int kk = p / 48, nc = (p % 48) * 2;
        uint2 v = *(const uint2*)(W1cp + (size_t)kk*96 + nc);
        *(unsigned*)&Wh[kk*104+nc] = __byte_perm(v.x, v.y, 0x5410);
        *(unsigned*)&Wl[kk*104+nc] = __byte_perm(v.x, v.y, 0x7632);
    }
    __syncthreads();

    wmma::fragment<wmma::accumulator,16,16,16,float> acc[2][3];
    #pragma unroll
    for (int i = 0; i < 2; i++)
        #pragma unroll
        for (int j = 0; j < 3; j++) wmma::fill_fragment(acc[i][j], 0.f);
    do_mma32(acc, Ah, Al, Wh, Wl, wm, wn);
    __syncthreads();
    #pragma unroll
    for (int i = 0; i < 2; i++)
        #pragma unroll
        for (int j = 0; j < 3; j++)
            wmma::store_matrix_sync(&pes[(wm + i*16)*96 + wn + j*16], acc[i][j], 96,
                                    wmma::mem_row_major);
    __syncthreads();

    int base = wid * 16;
    int cur = -1;
    float a0 = 0.f, a1 = 0.f, a2 = 0.f, p0 = 0.f, p1 = 0.f, p2 = 0.f;
    for (int j = 0; j < 16; j++) {
        int i = e0 + base + j;
        int t = ctgt[i], s = csrc[i];
        if (t != cur) {
            if (cur >= 0) {
                atomicAdd(&AGG[cur*96 + lane],      a0);
                atomicAdd(&AGG[cur*96 + lane + 32], a1);
                atomicAdd(&AGG[cur*96 + lane + 64], a2);
            }
            cur = t; a0 = a1 = a2 = 0.f;
            p0 = PT[t*96 + lane]; p1 = PT[t*96 + lane + 32]; p2 = PT[t*96 + lane + 64];
        }
        const float* pr = &pes[(base + j)*96];
        a0 += fmaxf(p0 + PS[s*96 + lane]      + pr[lane],      0.f);
        a1 += fmaxf(p1 + PS[s*96 + lane + 32] + pr[lane + 32], 0.f);
        a2 += fmaxf(p2 + PS[s*96 + lane + 64] + pr[lane + 64], 0.f);
    }
    if (cur >= 0) {
        atomicAdd(&AGG[cur*96 + lane],      a0);
        atomicAdd(&AGG[cur*96 + lane + 32], a1);
        atomicAdd(&AGG[cur*96 + lane + 64], a2);
    }
}

__global__ void pool_kernel(const unsigned* __restrict__ hp, const int* __restrict__ gstart,
                            unsigned* __restrict__ gmp) {
    int g = blockIdx.x, f = threadIdx.x;
    int beg = gstart[g], end = gstart[g+1];
    float s = 0.f;
    for (int r = beg; r < end; r++) {
        unsigned u = hp[(size_t)r*96 + f];
        s += __bfloat162float(__ushort_as_bfloat16((unsigned short)(u & 0xffff)))
           + __bfloat162float(__ushort_as_bfloat16((unsigned short)(u >> 16)));
    }
    s /= (float)max(end - beg, 1);
    gmp[g*96 + f] = packsplit(s);
}

// ------------------------------- host --------------------------------------
extern "C" void kernel_launch(void* const* d_in, const int* in_sizes, int n_in,
                              void* d_out, int out_size) {
    const float* x          = (const float*)d_in[0];
    const float* edge_attr  = (const float*)d_in[1];
    const int*   edge_index = (const int*)d_in[2];
    const int*   batch      = (const int*)d_in[3];
    const float* emb_w1 = (const float*)d_in[4];  const float* emb_b1 = (const float*)d_in[5];
    const float* emb_w2 = (const float*)d_in[6];  const float* emb_b2 = (const float*)d_in[7];
    const float* msg_w1 = (const float*)d_in[8];  const float* msg_b1 = (const float*)d_in[9];
    const float* msg_w2 = (const float*)d_in[10]; const float* msg_b2 = (const float*)d_in[11];
    const float* upd_w1 = (const float*)d_in[12]; const float* upd_b1 = (const float*)d_in[13];
    const float* upd_w2 = (const float*)d_in[14]; const float* upd_b2 = (const float*)d_in[15];
    const float* head_w1 = (const float*)d_in[16]; const float* head_b1 = (const float*)d_in[17];
    const float* head_w2 = (const float*)d_in[18]; const float* head_b2 = (const float*)d_in[19];

    static int smset = 0;
    if (!smset) {
        cudaFuncSetAttribute(mlp_tc, cudaFuncAttributeMaxDynamicSharedMemorySize, SMB);
        smset = 1;
    }

    float* f = nullptr; unsigned* pp = nullptr; unsigned* wp = nullptr; int* ib = nullptr;
    cudaGetSymbolAddress((void**)&f, d_f);
    cudaGetSymbolAddress((void**)&pp, d_p);
    cudaGetSymbolAddress((void**)&wp, d_wp);
    cudaGetSymbolAddress((void**)&ib, d_i);

    float* PT = f;  float* PS = f + NH;  float* AGG = f + 2*NH;  float* bcomb = f + 3*NH;

    unsigned* xp  = pp;
    unsigned* hp  = xp + NN*NFD;
    unsigned* h2p = hp + NH;
    unsigned* gmp = h2p + NH;
    unsigned* eap = gmp + GG*HH;

    unsigned* ewp1 = wp;                 // 64x96
    unsigned* ewp2 = ewp1 + 6144;        // 96x96
    unsigned* mwp  = ewp2 + 9216;        // 4 x 224x96
    unsigned* wu1p = mwp + 86016;        // 4 x 192x96
    unsigned* uw2p = wu1p + 73728;       // 4 x 96x96
    unsigned* hw1p = uw2p + 36864;       // 96x96
    unsigned* hw2p = hw1p + 9216;        // 96x64

    int* deg = ib;                 int* gcnt = deg + NN;
    int* rowptr = gcnt + GG + 1;   int* cursor = rowptr + NN + 1;
    int* srcs = cursor + NN;       int* ctgt = srcs + EE;
    int* eids = ctgt + EE;         int* gstart = eids + EE;

    const int* src = edge_index;
    const int* tgt = edge_index + EE;

    // 1. zero deg+gcnt (adjacent)
    cudaMemsetAsync(deg, 0, (NN + GG + 1)*sizeof(int));
    // 2. histograms
    hist_both<<<(EE + NN + 255)/256, 256>>>(tgt, batch, deg, gcnt);
    // 3. scans (+cursor copy)
    scan_both<<<1, 1024>>>(deg, rowptr, cursor, gcnt, gstart);
    // 4. counting-sort scatter
    scatter_kernel<<<(EE + 255)/256, 256>>>(src, tgt, cursor, srcs, eids, ctgt);
    // 5. split x + gather/split edge_attr
    gather_split<<<(NN*NFD + EE*EFD + 255)/256, 256>>>(x, edge_attr, eids, xp, eap);
    // 6. pack static weights
    {
        PackArgs a;
        a.src[0]=emb_w1;  a.dst[0]=ewp1; a.n[0]=NFD*HH;
        a.src[1]=emb_w2;  a.dst[1]=ewp2; a.n[1]=HH*HH;
        a.src[2]=msg_w1;  a.dst[2]=mwp;  a.n[2]=LL*(2*HH+EFD)*HH;
        for (int l = 0; l < LL; l++) {
            a.src[3+l] = upd_w1 + (size_t)l*2*HH*HH;
            a.dst[3+l] = wu1p + (size_t)l*2*HH*HH;
            a.n[3+l] = HH*HH;
        }
        a.src[7]=upd_w2;  a.dst[7]=uw2p; a.n[7]=LL*HH*HH;
        a.src[8]=head_w1; a.dst[8]=hw1p; a.n[8]=HH*HH;
        a.src[9]=head_w2; a.dst[9]=hw2p; a.n[9]=HH*OUTD;
        dim3 g((86016 + 255)/256, 10);
        pack_kernel<<<g, 256>>>(a);
    }
    // 7. Wcomb / bcomb
    wcomb_kernel<<<LL, 256>>>(msg_w2, msg_b2, upd_w1, wu1p, bcomb);

    int nb = (NN + 127)/128;
    // 8. embed (fused 2-stage): hp = mlp2(x)
    mlp_tc<<<nb, 256, SMB>>>(xp, NFD, NFD, NFD, nullptr, 0, nullptr, 0,
                             ewp1, nullptr, emb_b1, nullptr, nullptr, nullptr, 1,
                             ewp2, emb_b2, HH, 0,
                             nullptr, nullptr, hp, HH, NN);

    unsigned* hc = hp;
    unsigned* hn = h2p;
    for (int l = 0; l < LL; l++) {
        const unsigned* mw = mwp + (size_t)l*(2*HH+EFD)*HH;
        // PT/PS dual single-stage GEMM
        mlp_tc<<<dim3(nb,2), 256, SMB>>>(hc, HH, HH, HH, nullptr, 0, nullptr, 0,
                                         mw, mw + HH*HH, msg_b1 + l*HH, nullptr,
                                         nullptr, nullptr, 0,
                                         nullptr, nullptr, 0, 0,
                                         PT, PS, nullptr, HH, NN);
        // edge: AGG += relu(PT[tgt]+PS[src]+ea@W1c)  (AGG pre-zeroed by prev update)
        edge_fused<<<EE/128, 256>>>(eap, mw + 2*HH*HH, PT, PS, srcs, ctgt, AGG);
        // update (fused 2-stage, K=192, AGG consumed+zeroed, Wcomb folded)
        mlp_tc<<<nb, 256, SMB>>>(hc, HH, HH, 2*HH, AGG, HH, deg, 1,
                                 wu1p + (size_t)l*2*HH*HH, nullptr,
                                 upd_b1 + l*HH, nullptr, bcomb + l*HH, deg, 1,
                                 uw2p + (size_t)l*HH*HH, upd_b2 + l*HH, HH, 0,
                                 nullptr, nullptr, hn, HH, NN);
        unsigned* t = hc; hc = hn; hn = t;
    }

    // pool + head (fused 2-stage)
    pool_kernel<<<GG, HH>>>(hc, gstart, gmp);
    mlp_tc<<<1, 256, SMB>>>(gmp, HH, HH, HH, nullptr, 0, nullptr, 0,
                            hw1p, nullptr, head_b1, nullptr, nullptr, nullptr, 1,
                            hw2p, head_b2, OUTD, 0,
                            (float*)d_out, nullptr, nullptr, OUTD, GG);
}